// round 4
// baseline (speedup 1.0000x reference)
#include <cuda_runtime.h>
#include <math.h>

#define BB 2
#define SS 2048
#define DD 1024
#define HH 16
#define DH 64
#define MROWS (BB*SS)   // 4096
#define BQ 64
#define BK 64

typedef unsigned long long ull;

// Scratch (16 MB each):
__device__ float g_Q [BB*HH*SS*DH];   // Q natural  [bh][s][d]   (also the "values")
__device__ float g_K [BB*HH*SS*DH];   // K raw      [bh][s][d]
__device__ float g_Qt[BB*HH*DH*SS];   // Q transposed [bh][d][s]
__device__ float g_Kt[BB*HH*DH*SS];   // fused K transposed [bh][d][s]

__device__ __forceinline__ float logsig(float x) {
    return fminf(x, 0.0f) - log1pf(expf(-fabsf(x)));
}

// ---- packed f32x2 helpers -------------------------------------------------
__device__ __forceinline__ ull pack2(float x, float y) {
    ull r; asm("mov.b64 %0, {%1, %2};" : "=l"(r) : "f"(x), "f"(y)); return r;
}
__device__ __forceinline__ ull dup2(float x) {
    ull r; asm("mov.b64 %0, {%1, %1};" : "=l"(r) : "f"(x)); return r;
}
__device__ __forceinline__ void unpack2(ull v, float& x, float& y) {
    asm("mov.b64 {%0, %1}, %2;" : "=f"(x), "=f"(y) : "l"(v));
}
__device__ __forceinline__ ull ffma2(ull a, ull b, ull c) {
    ull d; asm("fma.rn.f32x2 %0, %1, %2, %3;" : "=l"(d) : "l"(a), "l"(b), "l"(c)); return d;
}
__device__ __forceinline__ ull fmul2(ull a, ull b) {
    ull d; asm("mul.rn.f32x2 %0, %1, %2;" : "=l"(d) : "l"(a), "l"(b)); return d;
}

// ---------------------------------------------------------------------------
// GEMM: C[m,n] = sum_k A[m,k]*W[k,n] + bias[n], scattered to dst[b][h][s][d]
// BM=BN=128, BK=16, 256 threads, 8x8 microtile, packed f32x2 FMA.
// ---------------------------------------------------------------------------
__global__ __launch_bounds__(256) void qk_gemm(
    const float* __restrict__ A, const float* __restrict__ W,
    const float* __restrict__ bias, float* __restrict__ dst)
{
    __shared__ float As[16][128];   // [k][m]
    __shared__ float Bs[16][128];   // [k][n]

    const int tid = threadIdx.x;
    const int m0 = blockIdx.y * 128;
    const int n0 = blockIdx.x * 128;
    const int ty = tid >> 4;        // 0..15
    const int tx = tid & 15;        // 0..15

    ull acc[8][4];
    #pragma unroll
    for (int i = 0; i < 8; i++)
        #pragma unroll
        for (int j = 0; j < 4; j++) acc[i][j] = 0ull;

    for (int k0 = 0; k0 < DD; k0 += 16) {
        #pragma unroll
        for (int i = 0; i < 2; i++) {
            int idx = tid + i * 256;
            int row = idx >> 2;
            int c4  = idx & 3;
            float4 v = *(const float4*)&A[(size_t)(m0 + row) * DD + k0 + c4 * 4];
            As[c4*4+0][row] = v.x;
            As[c4*4+1][row] = v.y;
            As[c4*4+2][row] = v.z;
            As[c4*4+3][row] = v.w;
        }
        #pragma unroll
        for (int i = 0; i < 2; i++) {
            int idx = tid + i * 256;
            int row = idx >> 5;
            int c4  = idx & 31;
            *(float4*)&Bs[row][c4*4] =
                *(const float4*)&W[(size_t)(k0 + row) * DD + n0 + c4 * 4];
        }
        __syncthreads();

        #pragma unroll
        for (int k = 0; k < 16; k++) {
            float4 a0 = *(const float4*)&As[k][ty*8];
            float4 a1 = *(const float4*)&As[k][ty*8+4];
            float4 b0 = *(const float4*)&Bs[k][tx*8];
            float4 b1 = *(const float4*)&Bs[k][tx*8+4];
            ull bb[4] = { pack2(b0.x,b0.y), pack2(b0.z,b0.w),
                          pack2(b1.x,b1.y), pack2(b1.z,b1.w) };
            ull aa[8] = { dup2(a0.x), dup2(a0.y), dup2(a0.z), dup2(a0.w),
                          dup2(a1.x), dup2(a1.y), dup2(a1.z), dup2(a1.w) };
            #pragma unroll
            for (int i = 0; i < 8; i++)
                #pragma unroll
                for (int j = 0; j < 4; j++)
                    acc[i][j] = ffma2(aa[i], bb[j], acc[i][j]);
        }
        __syncthreads();
    }

    #pragma unroll
    for (int i = 0; i < 8; i++) {
        int m = m0 + ty*8 + i;
        int b = m >> 11;
        int s = m & (SS - 1);
        #pragma unroll
        for (int j = 0; j < 4; j++) {
            float c0, c1;
            unpack2(acc[i][j], c0, c1);
            int n = n0 + tx*8 + j*2;
            int h0 = n >> 6, d0 = n & (DH - 1);
            int h1 = (n+1) >> 6, d1 = (n+1) & (DH - 1);
            dst[(((size_t)b * HH + h0) * SS + s) * DH + d0] = c0 + bias[n];
            dst[(((size_t)b * HH + h1) * SS + s) * DH + d1] = c1 + bias[n+1];
        }
    }
}

// ---------------------------------------------------------------------------
// Fused pointwise + transpose:
//   g_Kt[bh][d][s] = logsig(logsig(q) + q + kraw)
//   g_Qt[bh][d][s] = q
// Block: one 64(s) x 64(d) tile per bh. 256 threads.
// ---------------------------------------------------------------------------
__global__ __launch_bounds__(256) void fuse_transpose()
{
    __shared__ float tq[64][65];
    __shared__ float tk[64][65];

    const int bh = blockIdx.y;
    const int s0 = blockIdx.x * 64;
    const int tid = threadIdx.x;

    const float4* Qsrc = (const float4*)(g_Q + (size_t)bh*SS*DH + (size_t)s0*DH);
    const float4* Ksrc = (const float4*)(g_K + (size_t)bh*SS*DH + (size_t)s0*DH);

    #pragma unroll
    for (int i = 0; i < 4; i++) {
        int idx4 = tid + i * 256;       // 0..1023
        int row  = idx4 >> 4;           // s within tile
        int c    = (idx4 & 15) * 4;     // d
        float4 q = Qsrc[idx4];
        float4 k = Ksrc[idx4];
        float f0 = logsig(logsig(q.x) + q.x + k.x);
        float f1 = logsig(logsig(q.y) + q.y + k.y);
        float f2 = logsig(logsig(q.z) + q.z + k.z);
        float f3 = logsig(logsig(q.w) + q.w + k.w);
        tq[row][c+0] = q.x; tq[row][c+1] = q.y; tq[row][c+2] = q.z; tq[row][c+3] = q.w;
        tk[row][c+0] = f0;  tk[row][c+1] = f1;  tk[row][c+2] = f2;  tk[row][c+3] = f3;
    }
    __syncthreads();

    // write transposed: rows d, cols s (coalesced)
    const int d  = tid >> 2;            // 0..63
    const int sq = (tid & 3) * 16;      // 0,16,32,48
    float* Qdst = g_Qt + (size_t)bh*DH*SS + (size_t)d*SS + s0 + sq;
    float* Kdst = g_Kt + (size_t)bh*DH*SS + (size_t)d*SS + s0 + sq;
    #pragma unroll
    for (int c = 0; c < 16; c += 4) {
        float4 vq, vk;
        vq.x = tq[sq+c+0][d]; vq.y = tq[sq+c+1][d]; vq.z = tq[sq+c+2][d]; vq.w = tq[sq+c+3][d];
        vk.x = tk[sq+c+0][d]; vk.y = tk[sq+c+1][d]; vk.z = tk[sq+c+2][d]; vk.w = tk[sq+c+3][d];
        *(float4*)(Qdst + c) = vq;
        *(float4*)(Kdst + c) = vk;
    }
}

// ---------------------------------------------------------------------------
// Flash attention, register-tiled, packed f32x2.
// Block: 64 queries, iterates 64-key tiles. 128 threads = 16(ty) x 8(tx).
// Thread owns 4 q-rows x 8 k-cols (scores) and 4 q-rows x 8 d-cols (O).
// smem: Qs[d][qi] 16KB | KPs (Ks[d][kj] then Ps[j][qi]) 16KB | Vs[j][d] 16KB.
// ---------------------------------------------------------------------------
__global__ __launch_bounds__(128) void attn(
    const int* __restrict__ mask, float* __restrict__ out)
{
    __shared__ float Qs [64][64];
    __shared__ float KPs[64][64];
    __shared__ float Vs [64][64];

    const int bh = blockIdx.y;
    const int b  = bh >> 4;
    const int h  = bh & (HH - 1);
    const int q0 = blockIdx.x * BQ;
    const int tid = threadIdx.x;
    const int ty = tid >> 3;   // 0..15
    const int tx = tid & 7;    // 0..7

    const float* __restrict__ Qt = g_Qt + (size_t)bh * DH * SS;
    const float* __restrict__ Kt = g_Kt + (size_t)bh * DH * SS;
    const float* __restrict__ Qn = g_Q  + (size_t)bh * SS * DH;

    // stage query tile: Qs[d][qi]
    {
        int row = tid >> 1, half = tid & 1;
        const float4* src = (const float4*)(Qt + (size_t)row * SS + q0 + half * 32);
        float4* dst = (float4*)&Qs[row][half * 32];
        #pragma unroll
        for (int i = 0; i < 8; i++) dst[i] = src[i];
    }

    bool mq[4];
    #pragma unroll
    for (int i = 0; i < 4; i++) mq[i] = (mask[b * SS + q0 + ty*4 + i] == 0);

    float m[4], l[4];
    ull acc[4][4];
    #pragma unroll
    for (int i = 0; i < 4; i++) {
        m[i] = -1e30f; l[i] = 0.0f;
        #pragma unroll
        for (int j = 0; j < 4; j++) acc[i][j] = 0ull;
    }

    for (int t0 = 0; t0 < SS; t0 += BK) {
        __syncthreads();   // previous tile's PV reads done before restaging
        {
            int row = tid >> 1, half = tid & 1;
            const float4* srcK = (const float4*)(Kt + (size_t)row * SS + t0 + half * 32);
            float4* dstK = (float4*)&KPs[row][half * 32];
            #pragma unroll
            for (int i = 0; i < 8; i++) dstK[i] = srcK[i];
            const float4* srcV = (const float4*)(Qn + (size_t)t0 * DH);
            float4* dstV = (float4*)Vs;
            #pragma unroll
            for (int i = 0; i < 8; i++) dstV[tid + i * 128] = srcV[tid + i * 128];
        }
        __syncthreads();

        // ---- S = Q.K^T  (64 d-steps) ----
        ull s2[4][4];
        #pragma unroll
        for (int i = 0; i < 4; i++)
            #pragma unroll
            for (int j = 0; j < 4; j++) s2[i][j] = 0ull;

        #pragma unroll 4
        for (int d = 0; d < 64; d++) {
            float4 av = *(const float4*)&Qs[d][ty*4];
            float4 b0 = *(const float4*)&KPs[d][tx*8];
            float4 b1 = *(const float4*)&KPs[d][tx*8+4];
            ull bb[4] = { pack2(b0.x,b0.y), pack2(b0.z,b0.w),
                          pack2(b1.x,b1.y), pack2(b1.z,b1.w) };
            ull aa[4] = { dup2(av.x), dup2(av.y), dup2(av.z), dup2(av.w) };
            #pragma unroll
            for (int i = 0; i < 4; i++)
                #pragma unroll
                for (int j = 0; j < 4; j++)
                    s2[i][j] = ffma2(aa[i], bb[j], s2[i][j]);
        }

        // ---- online softmax on 4x8 score tile ----
        float p[4][8];
        #pragma unroll
        for (int i = 0; i < 4; i++) {
            float s[8];
            #pragma unroll
            for (int j = 0; j < 4; j++) unpack2(s2[i][j], s[2*j], s[2*j+1]);
            #pragma unroll
            for (int j = 0; j < 8; j++)
                s[j] = mq[i] ? -10000.0f : s[j] * -0.125f;

            float tm = s[0];
            #pragma unroll
            for (int j = 1; j < 8; j++) tm = fmaxf(tm, s[j]);
            #pragma unroll
            for (int o = 1; o < 8; o <<= 1)
                tm = fmaxf(tm, __shfl_xor_sync(0xffffffffu, tm, o));

            float mn = fmaxf(m[i], tm);
            float corr = __expf(m[i] - mn);
            m[i] = mn;

            float rs = 0.0f;
            #pragma unroll
            for (int j = 0; j < 8; j++) {
                p[i][j] = __expf(s[j] - mn);
                rs += p[i][j];
            }
            #pragma unroll
            for (int o = 1; o < 8; o <<= 1)
                rs += __shfl_xor_sync(0xffffffffu, rs, o);

            l[i] = l[i] * corr + rs;
            ull c2 = dup2(corr);
            #pragma unroll
            for (int j = 0; j < 4; j++) acc[i][j] = fmul2(acc[i][j], c2);
        }

        __syncthreads();   // all S-GEMM reads of KPs done
        // write P transposed: Ps[j][qi]
        #pragma unroll
        for (int j = 0; j < 8; j++) {
            float4 v = make_float4(p[0][j], p[1][j], p[2][j], p[3][j]);
            *(float4*)&KPs[tx*8 + j][ty*4] = v;
        }
        __syncthreads();

        // ---- O += P.V  (64 j-steps) ----
        #pragma unroll 4
        for (int j = 0; j < 64; j++) {
            float4 pv = *(const float4*)&KPs[j][ty*4];
            float4 v0 = *(const float4*)&Vs[j][tx*8];
            float4 v1 = *(const float4*)&Vs[j][tx*8+4];
            ull vv[4] = { pack2(v0.x,v0.y), pack2(v0.z,v0.w),
                          pack2(v1.x,v1.y), pack2(v1.z,v1.w) };
            ull pp[4] = { dup2(pv.x), dup2(pv.y), dup2(pv.z), dup2(pv.w) };
            #pragma unroll
            for (int i = 0; i < 4; i++)
                #pragma unroll
                for (int jj = 0; jj < 4; jj++)
                    acc[i][jj] = ffma2(pp[i], vv[jj], acc[i][jj]);
        }
    }

    // epilogue
    #pragma unroll
    for (int i = 0; i < 4; i++) {
        float inv = 1.0f / l[i];
        int s = q0 + ty*4 + i;
        float* orow = out + ((size_t)b * SS + s) * (HH*DH) + h * DH + tx * 8;
        float o[8];
        #pragma unroll
        for (int j = 0; j < 4; j++) unpack2(acc[i][j], o[2*j], o[2*j+1]);
        float4 w0 = make_float4(o[0]*inv, o[1]*inv, o[2]*inv, o[3]*inv);
        float4 w1 = make_float4(o[4]*inv, o[5]*inv, o[6]*inv, o[7]*inv);
        *(float4*)(orow)     = w0;
        *(float4*)(orow + 4) = w1;
    }
}

// ---------------------------------------------------------------------------
extern "C" void kernel_launch(void* const* d_in, const int* in_sizes, int n_in,
                              void* d_out, int out_size)
{
    const float* hs   = (const float*)d_in[0];
    const int*   mask = (const int*)  d_in[1];
    const float* Wq   = (const float*)d_in[2];
    const float* bq   = (const float*)d_in[3];
    const float* Wk   = (const float*)d_in[4];
    const float* bk   = (const float*)d_in[5];
    float* out = (float*)d_out;

    void *qptr = nullptr, *kptr = nullptr;
    cudaGetSymbolAddress(&qptr, g_Q);
    cudaGetSymbolAddress(&kptr, g_K);

    dim3 ggrid(DD / 128, MROWS / 128);           // (8, 32)
    qk_gemm<<<ggrid, 256>>>(hs, Wq, bq, (float*)qptr);
    qk_gemm<<<ggrid, 256>>>(hs, Wk, bk, (float*)kptr);

    dim3 tgrid(SS / 64, BB * HH);                // (32, 32)
    fuse_transpose<<<tgrid, 256>>>();

    dim3 agrid(SS / BQ, BB * HH);                // (32, 32)
    attn<<<agrid, 128>>>(mask, out);
}

// round 5
// speedup vs baseline: 1.6177x; 1.6177x over previous
#include <cuda_runtime.h>
#include <math.h>

#define BB 2
#define SS 2048
#define DD 1024
#define HH 16
#define DH 64
#define MROWS (BB*SS)   // 4096

typedef unsigned long long ull;

// Scratch (16 MB each):
__device__ float g_Q [BB*HH*SS*DH];   // Q natural [bh][s][d] (also the values)
__device__ float g_K [BB*HH*SS*DH];   // K raw     [bh][s][d]
__device__ float g_Qt[BB*HH*DH*SS];   // (-Q/8) transposed [bh][d][s]
__device__ float g_Kt[BB*HH*DH*SS];   // fused K transposed [bh][d][s]

__device__ __forceinline__ float logsig(float x) {
    return fminf(x, 0.0f) - log1pf(expf(-fabsf(x)));
}

// ---- packed f32x2 helpers -------------------------------------------------
__device__ __forceinline__ ull pack2(float x, float y) {
    ull r; asm("mov.b64 %0, {%1, %2};" : "=l"(r) : "f"(x), "f"(y)); return r;
}
__device__ __forceinline__ ull dup2(float x) {
    ull r; asm("mov.b64 %0, {%1, %1};" : "=l"(r) : "f"(x)); return r;
}
__device__ __forceinline__ void unpack2(ull v, float& x, float& y) {
    asm("mov.b64 {%0, %1}, %2;" : "=f"(x), "=f"(y) : "l"(v));
}
__device__ __forceinline__ ull ffma2(ull a, ull b, ull c) {
    ull d; asm("fma.rn.f32x2 %0, %1, %2, %3;" : "=l"(d) : "l"(a), "l"(b), "l"(c)); return d;
}

// ---------------------------------------------------------------------------
// GEMM: C[m,n] = sum_k A[m,k]*W[k,n] + bias[n], scattered to dst[b][h][s][d]
// BM=BN=128, BK=16, 256 threads, 8x8 microtile (k-cols split tx*4 / 64+tx*4
// for conflict-free LDS), packed f32x2 FMA.
// ---------------------------------------------------------------------------
__global__ __launch_bounds__(256) void qk_gemm(
    const float* __restrict__ A, const float* __restrict__ W,
    const float* __restrict__ bias, float* __restrict__ dst)
{
    __shared__ float As[16][128];   // [k][m]
    __shared__ float Bs[16][128];   // [k][n]

    const int tid = threadIdx.x;
    const int m0 = blockIdx.y * 128;
    const int n0 = blockIdx.x * 128;
    const int ty = tid >> 4;        // 0..15
    const int tx = tid & 15;        // 0..15

    ull acc[8][4];
    #pragma unroll
    for (int i = 0; i < 8; i++)
        #pragma unroll
        for (int j = 0; j < 4; j++) acc[i][j] = 0ull;

    for (int k0 = 0; k0 < DD; k0 += 16) {
        #pragma unroll
        for (int i = 0; i < 2; i++) {
            int idx = tid + i * 256;
            int row = idx >> 2;
            int c4  = idx & 3;
            float4 v = *(const float4*)&A[(size_t)(m0 + row) * DD + k0 + c4 * 4];
            As[c4*4+0][row] = v.x;
            As[c4*4+1][row] = v.y;
            As[c4*4+2][row] = v.z;
            As[c4*4+3][row] = v.w;
        }
        #pragma unroll
        for (int i = 0; i < 2; i++) {
            int idx = tid + i * 256;
            int row = idx >> 5;
            int c4  = idx & 31;
            *(float4*)&Bs[row][c4*4] =
                *(const float4*)&W[(size_t)(k0 + row) * DD + n0 + c4 * 4];
        }
        __syncthreads();

        #pragma unroll
        for (int k = 0; k < 16; k++) {
            float4 a0 = *(const float4*)&As[k][ty*8];
            float4 a1 = *(const float4*)&As[k][ty*8+4];
            float4 b0 = *(const float4*)&Bs[k][tx*4];        // contiguous: no conflict
            float4 b1 = *(const float4*)&Bs[k][64 + tx*4];   // contiguous: no conflict
            ull bb[4] = { pack2(b0.x,b0.y), pack2(b0.z,b0.w),
                          pack2(b1.x,b1.y), pack2(b1.z,b1.w) };
            float av[8] = { a0.x,a0.y,a0.z,a0.w, a1.x,a1.y,a1.z,a1.w };
            #pragma unroll
            for (int i = 0; i < 8; i++) {
                ull aa = dup2(av[i]);
                #pragma unroll
                for (int j = 0; j < 4; j++)
                    acc[i][j] = ffma2(aa, bb[j], acc[i][j]);
            }
        }
        __syncthreads();
    }

    #pragma unroll
    for (int i = 0; i < 8; i++) {
        int m = m0 + ty*8 + i;
        int b = m >> 11;
        int s = m & (SS - 1);
        float c[8];
        #pragma unroll
        for (int j = 0; j < 4; j++) unpack2(acc[i][j], c[2*j], c[2*j+1]);
        #pragma unroll
        for (int g = 0; g < 2; g++) {
            int nb = n0 + g * 64 + tx * 4;
            int h = nb >> 6, d = nb & (DH - 1);
            float4 v;
            v.x = c[g*4+0] + bias[nb+0];
            v.y = c[g*4+1] + bias[nb+1];
            v.z = c[g*4+2] + bias[nb+2];
            v.w = c[g*4+3] + bias[nb+3];
            *(float4*)&dst[(((size_t)b * HH + h) * SS + s) * DH + d] = v;
        }
    }
}

// ---------------------------------------------------------------------------
// Fused pointwise + transpose:
//   g_Kt[bh][d][s] = logsig(logsig(q) + q + kraw)
//   g_Qt[bh][d][s] = q * (-1/8)      (score scale folded in)
// ---------------------------------------------------------------------------
__global__ __launch_bounds__(256) void fuse_transpose()
{
    __shared__ float tq[64][65];
    __shared__ float tk[64][65];

    const int bh = blockIdx.y;
    const int s0 = blockIdx.x * 64;
    const int tid = threadIdx.x;

    const float4* Qsrc = (const float4*)(g_Q + (size_t)bh*SS*DH + (size_t)s0*DH);
    const float4* Ksrc = (const float4*)(g_K + (size_t)bh*SS*DH + (size_t)s0*DH);

    #pragma unroll
    for (int i = 0; i < 4; i++) {
        int idx4 = tid + i * 256;       // 0..1023
        int row  = idx4 >> 4;           // s within tile
        int c    = (idx4 & 15) * 4;     // d
        float4 q = Qsrc[idx4];
        float4 k = Ksrc[idx4];
        tq[row][c+0] = q.x * -0.125f;
        tq[row][c+1] = q.y * -0.125f;
        tq[row][c+2] = q.z * -0.125f;
        tq[row][c+3] = q.w * -0.125f;
        tk[row][c+0] = logsig(logsig(q.x) + q.x + k.x);
        tk[row][c+1] = logsig(logsig(q.y) + q.y + k.y);
        tk[row][c+2] = logsig(logsig(q.z) + q.z + k.z);
        tk[row][c+3] = logsig(logsig(q.w) + q.w + k.w);
    }
    __syncthreads();

    const int d  = tid >> 2;            // 0..63
    const int sq = (tid & 3) * 16;      // 0,16,32,48
    float* Qdst = g_Qt + (size_t)bh*DH*SS + (size_t)d*SS + s0 + sq;
    float* Kdst = g_Kt + (size_t)bh*DH*SS + (size_t)d*SS + s0 + sq;
    #pragma unroll
    for (int c = 0; c < 16; c += 4) {
        float4 vq, vk;
        vq.x = tq[sq+c+0][d]; vq.y = tq[sq+c+1][d]; vq.z = tq[sq+c+2][d]; vq.w = tq[sq+c+3][d];
        vk.x = tk[sq+c+0][d]; vk.y = tk[sq+c+1][d]; vk.z = tk[sq+c+2][d]; vk.w = tk[sq+c+3][d];
        *(float4*)(Qdst + c) = vq;
        *(float4*)(Kdst + c) = vk;
    }
}

// ---------------------------------------------------------------------------
// Flash attention without max-tracking (scores bounded -> exp safe in fp32).
// Block: BQ=64 queries x full DH, loops BK=128 key tiles. 128 threads.
// ty = tid>>4 (8 q-rows each), tx = tid&15.
//   S-GEMM micro: 8q x 8k  (k-cols = {tx*4..+3, 64+tx*4..+3})
//   PV   micro: 8q x 4d  (d-cols = tx*4..+3)
// smem: Qs[64d][64q] | Ks[64d][128k] | Vs[128k][64d] | Ps[128k][64q] = 112KB
// -> 2 blocks/SM.
// ---------------------------------------------------------------------------
__global__ __launch_bounds__(128) void attn(
    const int* __restrict__ mask, float* __restrict__ out)
{
    extern __shared__ float sm[];
    float* Qs = sm;                     // 64*64
    float* Ks = sm + 64*64;             // 64*128
    float* Vs = Ks + 64*128;            // 128*64
    float* Ps = Vs + 128*64;            // 128*64

    const int bh = blockIdx.y;
    const int b  = bh >> 4;
    const int h  = bh & (HH - 1);
    const int q0 = blockIdx.x * 64;
    const int tid = threadIdx.x;
    const int ty = tid >> 4;   // 0..7
    const int tx = tid & 15;   // 0..15

    const float* __restrict__ Qt = g_Qt + (size_t)bh * DH * SS;
    const float* __restrict__ Kt = g_Kt + (size_t)bh * DH * SS;
    const float* __restrict__ Vn = g_Q  + (size_t)bh * SS * DH;

    // stage Q tile: Qs[d][q]  (pre-scaled by -1/8)
    #pragma unroll
    for (int i = 0; i < 8; i++) {
        int idx = tid + i * 128;        // 0..1023
        int row = idx >> 4;             // d
        int c   = (idx & 15) * 4;       // q
        *(float4*)&Qs[row*64 + c] = *(const float4*)&Qt[(size_t)row * SS + q0 + c];
    }

    bool mq[8];
    #pragma unroll
    for (int i = 0; i < 8; i++) mq[i] = (mask[b * SS + q0 + ty*8 + i] == 0);

    float l[8];
    ull o[8][2];
    #pragma unroll
    for (int i = 0; i < 8; i++) { l[i] = 0.0f; o[i][0] = 0ull; o[i][1] = 0ull; }

    for (int t0 = 0; t0 < SS; t0 += 128) {
        __syncthreads();   // prior tile PV/S reads done (first iter: Qs staged)
        #pragma unroll
        for (int i = 0; i < 16; i++) {
            int idx = tid + i * 128;    // 0..2047
            int rk = idx >> 5;          // 0..63
            int ck = (idx & 31) * 4;
            *(float4*)&Ks[rk*128 + ck] = *(const float4*)&Kt[(size_t)rk * SS + t0 + ck];
            int rv = idx >> 4;          // 0..127
            int cv = (idx & 15) * 4;
            *(float4*)&Vs[rv*64 + cv] = *(const float4*)&Vn[(size_t)(t0 + rv) * DH + cv];
        }
        __syncthreads();

        // ---- S = (-Q/8) . K^T : 8q x 8k per thread ----
        ull s2[8][4];
        #pragma unroll
        for (int i = 0; i < 8; i++)
            #pragma unroll
            for (int j = 0; j < 4; j++) s2[i][j] = 0ull;

        #pragma unroll 8
        for (int d = 0; d < 64; d++) {
            float4 a0 = *(const float4*)&Qs[d*64 + ty*8];
            float4 a1 = *(const float4*)&Qs[d*64 + ty*8 + 4];
            float4 b0 = *(const float4*)&Ks[d*128 + tx*4];       // k = tx*4..
            float4 b1 = *(const float4*)&Ks[d*128 + 64 + tx*4];  // k = 64+tx*4..
            ull bb[4] = { pack2(b0.x,b0.y), pack2(b0.z,b0.w),
                          pack2(b1.x,b1.y), pack2(b1.z,b1.w) };
            float av[8] = { a0.x,a0.y,a0.z,a0.w, a1.x,a1.y,a1.z,a1.w };
            #pragma unroll
            for (int i = 0; i < 8; i++) {
                ull aa = dup2(av[i]);
                #pragma unroll
                for (int j = 0; j < 4; j++)
                    s2[i][j] = ffma2(aa, bb[j], s2[i][j]);
            }
        }

        // ---- p = exp(s) (no max subtraction), accumulate l ----
        float p[8][8];
        #pragma unroll
        for (int i = 0; i < 8; i++) {
            float s[8];
            #pragma unroll
            for (int j = 0; j < 4; j++) unpack2(s2[i][j], s[2*j], s[2*j+1]);
            #pragma unroll
            for (int j = 0; j < 8; j++) {
                float sv = mq[i] ? 0.0f : s[j];
                float pv = __expf(sv);
                p[i][j] = pv;
                l[i] += pv;
            }
        }

        // ---- write P transposed: Ps[k][q] ----
        #pragma unroll
        for (int jj = 0; jj < 4; jj++) {
            int k1 = tx*4 + jj;
            float4 w0 = make_float4(p[0][jj], p[1][jj], p[2][jj], p[3][jj]);
            float4 w1 = make_float4(p[4][jj], p[5][jj], p[6][jj], p[7][jj]);
            *(float4*)&Ps[k1*64 + ty*8]     = w0;
            *(float4*)&Ps[k1*64 + ty*8 + 4] = w1;
            int k2 = 64 + tx*4 + jj;
            float4 u0 = make_float4(p[0][4+jj], p[1][4+jj], p[2][4+jj], p[3][4+jj]);
            float4 u1 = make_float4(p[4][4+jj], p[5][4+jj], p[6][4+jj], p[7][4+jj]);
            *(float4*)&Ps[k2*64 + ty*8]     = u0;
            *(float4*)&Ps[k2*64 + ty*8 + 4] = u1;
        }
        __syncthreads();

        // ---- O += P.V : 8q x 4d per thread ----
        #pragma unroll 8
        for (int k = 0; k < 128; k++) {
            float4 p0 = *(const float4*)&Ps[k*64 + ty*8];
            float4 p1 = *(const float4*)&Ps[k*64 + ty*8 + 4];
            float4 v  = *(const float4*)&Vs[k*64 + tx*4];
            ull vv0 = pack2(v.x, v.y), vv1 = pack2(v.z, v.w);
            float pv[8] = { p0.x,p0.y,p0.z,p0.w, p1.x,p1.y,p1.z,p1.w };
            #pragma unroll
            for (int i = 0; i < 8; i++) {
                ull pp = dup2(pv[i]);
                o[i][0] = ffma2(pp, vv0, o[i][0]);
                o[i][1] = ffma2(pp, vv1, o[i][1]);
            }
        }
    }

    // reduce l across the 16 tx lanes (same ty group stays within half-warp)
    #pragma unroll
    for (int i = 0; i < 8; i++) {
        #pragma unroll
        for (int off = 1; off < 16; off <<= 1)
            l[i] += __shfl_xor_sync(0xffffffffu, l[i], off);
    }

    #pragma unroll
    for (int i = 0; i < 8; i++) {
        float inv = 1.0f / l[i];
        int s = q0 + ty*8 + i;
        float o0, o1, o2, o3;
        unpack2(o[i][0], o0, o1);
        unpack2(o[i][1], o2, o3);
        float4 w = make_float4(o0*inv, o1*inv, o2*inv, o3*inv);
        *(float4*)&out[((size_t)b * SS + s) * (HH*DH) + h * DH + tx*4] = w;
    }
}

// ---------------------------------------------------------------------------
extern "C" void kernel_launch(void* const* d_in, const int* in_sizes, int n_in,
                              void* d_out, int out_size)
{
    const float* hs   = (const float*)d_in[0];
    const int*   mask = (const int*)  d_in[1];
    const float* Wq   = (const float*)d_in[2];
    const float* bq   = (const float*)d_in[3];
    const float* Wk   = (const float*)d_in[4];
    const float* bk   = (const float*)d_in[5];
    float* out = (float*)d_out;

    void *qptr = nullptr, *kptr = nullptr;
    cudaGetSymbolAddress(&qptr, g_Q);
    cudaGetSymbolAddress(&kptr, g_K);

    dim3 ggrid(DD / 128, MROWS / 128);           // (8, 32)
    qk_gemm<<<ggrid, 256>>>(hs, Wq, bq, (float*)qptr);
    qk_gemm<<<ggrid, 256>>>(hs, Wk, bk, (float*)kptr);

    dim3 tgrid(SS / 64, BB * HH);                // (32, 32)
    fuse_transpose<<<tgrid, 256>>>();

    const int ATTN_SMEM = (64*64 + 64*128 + 128*64 + 128*64) * 4;   // 114688 B
    cudaFuncSetAttribute(attn, cudaFuncAttributeMaxDynamicSharedMemorySize, ATTN_SMEM);
    dim3 agrid(SS / 64, BB * HH);                // (32, 32)
    attn<<<agrid, 128, ATTN_SMEM>>>(mask, out);
}

// round 7
// speedup vs baseline: 2.7045x; 1.6718x over previous
#include <cuda_runtime.h>
#include <cuda_bf16.h>
#include <math.h>
#include <cstdint>

#define BB 2
#define SS 2048
#define DD 1024
#define HH 16
#define DH 64
#define MROWS (BB*SS)   // 4096

typedef unsigned long long ull;

// fp32 scratch (GEMM outputs)
__device__ float g_Q[BB*HH*SS*DH];    // Q natural [bh][s][d] (also the values)
__device__ float g_K[BB*HH*SS*DH];    // K raw     [bh][s][d]
// bf16 split operands
__device__ __nv_bfloat16 g_Khi[BB*HH*SS*DH];  // fused K, natural [bh][s][d]
__device__ __nv_bfloat16 g_Klo[BB*HH*SS*DH];
__device__ __nv_bfloat16 g_Vhi[BB*HH*DH*SS];  // V(=Q) transposed [bh][d][s]
__device__ __nv_bfloat16 g_Vlo[BB*HH*DH*SS];

__device__ __forceinline__ float logsig(float x) {
    return fminf(x, 0.0f) - log1pf(expf(-fabsf(x)));
}

// ---- packed f32x2 (projection GEMM) ---------------------------------------
__device__ __forceinline__ ull pack2(float x, float y) {
    ull r; asm("mov.b64 %0, {%1, %2};" : "=l"(r) : "f"(x), "f"(y)); return r;
}
__device__ __forceinline__ ull dup2(float x) {
    ull r; asm("mov.b64 %0, {%1, %1};" : "=l"(r) : "f"(x)); return r;
}
__device__ __forceinline__ void unpack2(ull v, float& x, float& y) {
    asm("mov.b64 {%0, %1}, %2;" : "=f"(x), "=f"(y) : "l"(v));
}
__device__ __forceinline__ ull ffma2(ull a, ull b, ull c) {
    ull d; asm("fma.rn.f32x2 %0, %1, %2, %3;" : "=l"(d) : "l"(a), "l"(b), "l"(c)); return d;
}

// ---- mma.sync / ldmatrix helpers (sm_80+ PTX, works at sm_103 base) -------
__device__ __forceinline__ uint32_t smem_u32(const void* p) {
    uint32_t a;
    asm("{ .reg .u64 t; cvta.to.shared.u64 t, %1; cvt.u32.u64 %0, t; }" : "=r"(a) : "l"(p));
    return a;
}
__device__ __forceinline__ void ldsm4(uint32_t* r, uint32_t addr) {
    asm volatile("ldmatrix.sync.aligned.m8n8.x4.shared.b16 {%0,%1,%2,%3}, [%4];"
        : "=r"(r[0]), "=r"(r[1]), "=r"(r[2]), "=r"(r[3]) : "r"(addr));
}
__device__ __forceinline__ void mma16816(float* c, const uint32_t* a, const uint32_t* b) {
    asm volatile(
        "mma.sync.aligned.m16n8k16.row.col.f32.bf16.bf16.f32 "
        "{%0,%1,%2,%3}, {%4,%5,%6,%7}, {%8,%9}, {%0,%1,%2,%3};"
        : "+f"(c[0]), "+f"(c[1]), "+f"(c[2]), "+f"(c[3])
        : "r"(a[0]), "r"(a[1]), "r"(a[2]), "r"(a[3]), "r"(b[0]), "r"(b[1]));
}
__device__ __forceinline__ void split_pair(float x, float y, uint32_t& hi, uint32_t& lo) {
    __nv_bfloat16 hx = __float2bfloat16(x), hy = __float2bfloat16(y);
    __nv_bfloat16 lx = __float2bfloat16(x - __bfloat162float(hx));
    __nv_bfloat16 ly = __float2bfloat16(y - __bfloat162float(hy));
    __nv_bfloat162 hv; hv.x = hx; hv.y = hy;
    __nv_bfloat162 lv; lv.x = lx; lv.y = ly;
    hi = *(const uint32_t*)&hv;
    lo = *(const uint32_t*)&lv;
}

// ---------------------------------------------------------------------------
// Projection GEMM (unchanged — known good)
// ---------------------------------------------------------------------------
__global__ __launch_bounds__(256) void qk_gemm(
    const float* __restrict__ A, const float* __restrict__ W,
    const float* __restrict__ bias, float* __restrict__ dst)
{
    __shared__ float As[16][128];
    __shared__ float Bs[16][128];

    const int tid = threadIdx.x;
    const int m0 = blockIdx.y * 128;
    const int n0 = blockIdx.x * 128;
    const int ty = tid >> 4;
    const int tx = tid & 15;

    ull acc[8][4];
    #pragma unroll
    for (int i = 0; i < 8; i++)
        #pragma unroll
        for (int j = 0; j < 4; j++) acc[i][j] = 0ull;

    for (int k0 = 0; k0 < DD; k0 += 16) {
        #pragma unroll
        for (int i = 0; i < 2; i++) {
            int idx = tid + i * 256;
            int row = idx >> 2;
            int c4  = idx & 3;
            float4 v = *(const float4*)&A[(size_t)(m0 + row) * DD + k0 + c4 * 4];
            As[c4*4+0][row] = v.x; As[c4*4+1][row] = v.y;
            As[c4*4+2][row] = v.z; As[c4*4+3][row] = v.w;
        }
        #pragma unroll
        for (int i = 0; i < 2; i++) {
            int idx = tid + i * 256;
            int row = idx >> 5;
            int c4  = idx & 31;
            *(float4*)&Bs[row][c4*4] =
                *(const float4*)&W[(size_t)(k0 + row) * DD + n0 + c4 * 4];
        }
        __syncthreads();

        #pragma unroll
        for (int k = 0; k < 16; k++) {
            float4 a0 = *(const float4*)&As[k][ty*8];
            float4 a1 = *(const float4*)&As[k][ty*8+4];
            float4 b0 = *(const float4*)&Bs[k][tx*4];
            float4 b1 = *(const float4*)&Bs[k][64 + tx*4];
            ull bb[4] = { pack2(b0.x,b0.y), pack2(b0.z,b0.w),
                          pack2(b1.x,b1.y), pack2(b1.z,b1.w) };
            float av[8] = { a0.x,a0.y,a0.z,a0.w, a1.x,a1.y,a1.z,a1.w };
            #pragma unroll
            for (int i = 0; i < 8; i++) {
                ull aa = dup2(av[i]);
                #pragma unroll
                for (int j = 0; j < 4; j++)
                    acc[i][j] = ffma2(aa, bb[j], acc[i][j]);
            }
        }
        __syncthreads();
    }

    #pragma unroll
    for (int i = 0; i < 8; i++) {
        int m = m0 + ty*8 + i;
        int b = m >> 11;
        int s = m & (SS - 1);
        float c[8];
        #pragma unroll
        for (int j = 0; j < 4; j++) unpack2(acc[i][j], c[2*j], c[2*j+1]);
        #pragma unroll
        for (int g = 0; g < 2; g++) {
            int nb = n0 + g * 64 + tx * 4;
            int h = nb >> 6, d = nb & (DH - 1);
            float4 v;
            v.x = c[g*4+0] + bias[nb+0];
            v.y = c[g*4+1] + bias[nb+1];
            v.z = c[g*4+2] + bias[nb+2];
            v.w = c[g*4+3] + bias[nb+3];
            *(float4*)&dst[(((size_t)b * HH + h) * SS + s) * DH + d] = v;
        }
    }
}

// ---------------------------------------------------------------------------
// Pointwise fused K -> bf16 hi/lo split (natural layout). 8 elems/thread.
// ---------------------------------------------------------------------------
__global__ __launch_bounds__(128) void split_k()
{
    const int i8 = blockIdx.x * 128 + threadIdx.x;
    const float4* Q = (const float4*)g_Q;
    const float4* K = (const float4*)g_K;
    float4 qa = Q[i8*2], qb = Q[i8*2+1];
    float4 ka = K[i8*2], kb = K[i8*2+1];
    float f[8] = {
        logsig(logsig(qa.x)+qa.x+ka.x), logsig(logsig(qa.y)+qa.y+ka.y),
        logsig(logsig(qa.z)+qa.z+ka.z), logsig(logsig(qa.w)+qa.w+ka.w),
        logsig(logsig(qb.x)+qb.x+kb.x), logsig(logsig(qb.y)+qb.y+kb.y),
        logsig(logsig(qb.z)+qb.z+kb.z), logsig(logsig(qb.w)+qb.w+kb.w) };
    __nv_bfloat16 hi[8], lo[8];
    #pragma unroll
    for (int j = 0; j < 8; j++) {
        hi[j] = __float2bfloat16(f[j]);
        lo[j] = __float2bfloat16(f[j] - __bfloat162float(hi[j]));
    }
    ((uint4*)g_Khi)[i8] = *(const uint4*)hi;
    ((uint4*)g_Klo)[i8] = *(const uint4*)lo;
}

// ---------------------------------------------------------------------------
// V(=Q) transpose to [bh][d][s] with bf16 hi/lo split. 64x64 tiles, 256 thr.
// ---------------------------------------------------------------------------
__global__ __launch_bounds__(256) void transpose_v()
{
    __shared__ float tq[64][65];
    const int bh = blockIdx.y;
    const int s0 = blockIdx.x * 64;
    const int tid = threadIdx.x;

    const float4* Qsrc = (const float4*)(g_Q + (size_t)bh*SS*DH + (size_t)s0*DH);
    #pragma unroll
    for (int i = 0; i < 4; i++) {
        int idx4 = tid + i * 256;
        int row  = idx4 >> 4;
        int c    = (idx4 & 15) * 4;
        float4 q = Qsrc[idx4];
        tq[row][c+0] = q.x; tq[row][c+1] = q.y; tq[row][c+2] = q.z; tq[row][c+3] = q.w;
    }
    __syncthreads();

    const int d  = tid >> 2;
    const int sq = (tid & 3) * 16;
    __nv_bfloat16 hi[16], lo[16];
    #pragma unroll
    for (int c = 0; c < 16; c++) {
        float v = tq[sq+c][d];
        hi[c] = __float2bfloat16(v);
        lo[c] = __float2bfloat16(v - __bfloat162float(hi[c]));
    }
    size_t off = (size_t)bh*DH*SS + (size_t)d*SS + s0 + sq;
    *(uint4*)(g_Vhi + off)     = *(const uint4*)hi;
    *(uint4*)(g_Vhi + off + 8) = *(const uint4*)(hi + 8);
    *(uint4*)(g_Vlo + off)     = *(const uint4*)lo;
    *(uint4*)(g_Vlo + off + 8) = *(const uint4*)(lo + 8);
}

// ---------------------------------------------------------------------------
// mma.sync flash attention. 256 threads = 8 warps; warp owns 16 q-rows.
// BQ=128, BK=128, 16 key-tiles. Q/P in register fragments, K/V^T in smem
// (XOR-swizzled), read via ldmatrix. No-max softmax (scores bounded).
// smem: KH[128][64]bf16 | KL | VH[64][128]bf16 | VL  = 64KB dynamic.
// ---------------------------------------------------------------------------
#define SM_KH 0
#define SM_KL 16384
#define SM_VH 32768
#define SM_VL 49152
#define ATTN_SMEM 65536

__global__ __launch_bounds__(256, 1) void attn(
    const int* __restrict__ mask, float* __restrict__ out)
{
    extern __shared__ char smem[];
    const uint32_t sb = smem_u32(smem);
    const int tid  = threadIdx.x;
    const int w    = tid >> 5;          // warp 0..7
    const int lane = tid & 31;
    const int bh = blockIdx.y;
    const int b  = bh >> 4;
    const int h  = bh & (HH - 1);
    const int q0 = blockIdx.x * 128;

    // ldmatrix lane geometry
    const int row_off = (lane & 7) + ((lane & 16) >> 1);  // 0..15
    const int khalf   = (lane >> 3) & 1;

    // ---- stage Q tile (fp32) into smem, then build A-fragments ----
    {
        float* Qs = (float*)smem;       // 128 x 64 fp32 = 32KB
        const float* src = g_Q + ((size_t)bh * SS + q0) * DH;
        #pragma unroll
        for (int i = 0; i < 8; i++) {
            int idx4 = tid + i * 256;   // 0..2047 float4
            ((float4*)Qs)[idx4] = ((const float4*)src)[idx4];
        }
        __syncthreads();
    }

    const int r0 = lane >> 2;           // 0..7
    const int cq = (lane & 3) * 2;
    uint32_t qh[4][4], ql[4][4];
    {
        const float* Qs = (const float*)smem;
        const int m0 = w * 16 + r0;     // local q row (0..127)
        #pragma unroll
        for (int ks = 0; ks < 4; ks++) {
            int c0 = ks * 16 + cq;
            float x0 = Qs[m0*64 + c0]     * -0.125f, y0 = Qs[m0*64 + c0 + 1]     * -0.125f;
            float x1 = Qs[(m0+8)*64 + c0] * -0.125f, y1 = Qs[(m0+8)*64 + c0 + 1] * -0.125f;
            float x2 = Qs[m0*64 + c0 + 8] * -0.125f, y2 = Qs[m0*64 + c0 + 9]     * -0.125f;
            float x3 = Qs[(m0+8)*64 + c0 + 8] * -0.125f, y3 = Qs[(m0+8)*64 + c0 + 9] * -0.125f;
            split_pair(x0, y0, qh[ks][0], ql[ks][0]);
            split_pair(x1, y1, qh[ks][1], ql[ks][1]);
            split_pair(x2, y2, qh[ks][2], ql[ks][2]);
            split_pair(x3, y3, qh[ks][3], ql[ks][3]);
        }
    }

    const bool mq0 = (mask[b * SS + q0 + w*16 + r0]     == 0);
    const bool mq1 = (mask[b * SS + q0 + w*16 + r0 + 8] == 0);

    float l0 = 0.0f, l1 = 0.0f;
    float oacc[8][4];
    #pragma unroll
    for (int j = 0; j < 8; j++)
        #pragma unroll
        for (int c = 0; c < 4; c++) oacc[j][c] = 0.0f;

    const uint4* Khi = (const uint4*)(g_Khi + (size_t)bh * SS * DH);
    const uint4* Klo = (const uint4*)(g_Klo + (size_t)bh * SS * DH);
    const uint4* Vhi = (const uint4*)(g_Vhi + (size_t)bh * DH * SS);
    const uint4* Vlo = (const uint4*)(g_Vlo + (size_t)bh * DH * SS);

    for (int t = 0; t < 16; t++) {
        const int t0 = t * 128;
        __syncthreads();   // prior tile's ldmatrix reads done (first: Q frag reads)

        // ---- stage K (128r x 128B) and V^T (64r x 256B), XOR-swizzled ----
        #pragma unroll
        for (int i = 0; i < 4; i++) {
            int c = tid + i * 256;              // 0..1023
            int rk = c >> 3, ck = c & 7;        // K: row, 16B chunk
            uint32_t kd = (uint32_t)(rk * 128 + ((ck ^ (rk & 7)) << 4));
            int ksrc = (t0 + rk) * 8 + ck;
            *(uint4*)(smem + SM_KH + kd) = Khi[ksrc];
            *(uint4*)(smem + SM_KL + kd) = Klo[ksrc];
            int rv = c >> 4, cv = c & 15;       // V: row (d), 16B chunk
            uint32_t vd = (uint32_t)(rv * 256 + ((cv ^ (rv & 7)) << 4));
            int vsrc = rv * (SS/8) + t0/8 + cv;
            *(uint4*)(smem + SM_VH + vd) = Vhi[vsrc];
            *(uint4*)(smem + SM_VL + vd) = Vlo[vsrc];
        }
        __syncthreads();

        // ---- S = Q.K^T : 16 n8-tiles x 4 ksteps, 3-product split ----
        float sacc[16][4];
        #pragma unroll
        for (int j = 0; j < 16; j++)
            #pragma unroll
            for (int c = 0; c < 4; c++) sacc[j][c] = 0.0f;

        #pragma unroll
        for (int ks = 0; ks < 4; ks++) {
            #pragma unroll
            for (int jp = 0; jp < 8; jp++) {
                int row = jp * 16 + row_off;
                int chunk = ks * 2 + khalf;
                uint32_t off = (uint32_t)(row * 128 + ((chunk ^ (row & 7)) << 4));
                uint32_t bh4[4], bl4[4];
                ldsm4(bh4, sb + SM_KH + off);
                ldsm4(bl4, sb + SM_KL + off);
                mma16816(sacc[2*jp],   qh[ks], bh4);
                mma16816(sacc[2*jp],   ql[ks], bh4);
                mma16816(sacc[2*jp],   qh[ks], bl4);
                mma16816(sacc[2*jp+1], qh[ks], bh4 + 2);
                mma16816(sacc[2*jp+1], ql[ks], bh4 + 2);
                mma16816(sacc[2*jp+1], qh[ks], bl4 + 2);
            }
        }

        // ---- softmax (no max) + convert P to A-fragments ----
        uint32_t phi[8][4], plo[8][4];
        #pragma unroll
        for (int kp = 0; kp < 8; kp++) {
            float p[8];
            #pragma unroll
            for (int half = 0; half < 2; half++) {
                const float* sc = sacc[2*kp + half];
                p[half*4+0] = __expf(mq0 ? 0.0f : sc[0]);
                p[half*4+1] = __expf(mq0 ? 0.0f : sc[1]);
                p[half*4+2] = __expf(mq1 ? 0.0f : sc[2]);
                p[half*4+3] = __expf(mq1 ? 0.0f : sc[3]);
            }
            l0 += p[0] + p[1] + p[4] + p[5];
            l1 += p[2] + p[3] + p[6] + p[7];
            split_pair(p[0], p[1], phi[kp][0], plo[kp][0]);
            split_pair(p[2], p[3], phi[kp][1], plo[kp][1]);
            split_pair(p[4], p[5], phi[kp][2], plo[kp][2]);
            split_pair(p[6], p[7], phi[kp][3], plo[kp][3]);
        }

        // ---- O += P.V : 8 d-tiles x 8 ksteps, 3-product split ----
        #pragma unroll
        for (int kp = 0; kp < 8; kp++) {
            #pragma unroll
            for (int jp = 0; jp < 4; jp++) {
                int row = jp * 16 + row_off;     // d rows 0..63
                int chunk = kp * 2 + khalf;      // of 16
                uint32_t off = (uint32_t)(row * 256 + ((chunk ^ (row & 7)) << 4));
                uint32_t vh4[4], vl4[4];
                ldsm4(vh4, sb + SM_VH + off);
                ldsm4(vl4, sb + SM_VL + off);
                mma16816(oacc[2*jp],   phi[kp], vh4);
                mma16816(oacc[2*jp],   plo[kp], vh4);
                mma16816(oacc[2*jp],   phi[kp], vl4);
                mma16816(oacc[2*jp+1], phi[kp], vh4 + 2);
                mma16816(oacc[2*jp+1], plo[kp], vh4 + 2);
                mma16816(oacc[2*jp+1], phi[kp], vl4 + 2);
            }
        }
    }

    // reduce l within row quads (lanes sharing l>>2)
    l0 += __shfl_xor_sync(0xffffffffu, l0, 1);
    l0 += __shfl_xor_sync(0xffffffffu, l0, 2);
    l1 += __shfl_xor_sync(0xffffffffu, l1, 1);
    l1 += __shfl_xor_sync(0xffffffffu, l1, 2);
    const float inv0 = 1.0f / l0;
    const float inv1 = 1.0f / l1;

    // ---- epilogue: scatter float2 per (row, d-tile) ----
    const int s0 = q0 + w*16 + r0;
    float* o0 = out + ((size_t)b * SS + s0)     * (HH*DH) + h * DH;
    float* o1 = out + ((size_t)b * SS + s0 + 8) * (HH*DH) + h * DH;
    #pragma unroll
    for (int j = 0; j < 8; j++) {
        int col = j * 8 + cq;
        float2 w0 = make_float2(oacc[j][0] * inv0, oacc[j][1] * inv0);
        float2 w1 = make_float2(oacc[j][2] * inv1, oacc[j][3] * inv1);
        *(float2*)(o0 + col) = w0;
        *(float2*)(o1 + col) = w1;
    }
}

// ---------------------------------------------------------------------------
extern "C" void kernel_launch(void* const* d_in, const int* in_sizes, int n_in,
                              void* d_out, int out_size)
{
    const float* hs   = (const float*)d_in[0];
    const int*   mask = (const int*)  d_in[1];
    const float* Wq   = (const float*)d_in[2];
    const float* bq   = (const float*)d_in[3];
    const float* Wk   = (const float*)d_in[4];
    const float* bk   = (const float*)d_in[5];
    float* out = (float*)d_out;

    void *qptr = nullptr, *kptr = nullptr;
    cudaGetSymbolAddress(&qptr, g_Q);
    cudaGetSymbolAddress(&kptr, g_K);

    dim3 ggrid(DD / 128, MROWS / 128);           // (8, 32)
    qk_gemm<<<ggrid, 256>>>(hs, Wq, bq, (float*)qptr);
    qk_gemm<<<ggrid, 256>>>(hs, Wk, bk, (float*)kptr);

    split_k<<<(BB*HH*SS*DH) / (128 * 8), 128>>>();
    dim3 tgrid(SS / 64, BB * HH);
    transpose_v<<<tgrid, 256>>>();

    cudaFuncSetAttribute(attn, cudaFuncAttributeMaxDynamicSharedMemorySize, ATTN_SMEM);
    dim3 agrid(SS / 128, BB * HH);               // (16, 32)
    attn<<<agrid, 256, ATTN_SMEM>>>(mask, out);
}